// round 6
// baseline (speedup 1.0000x reference)
#include <cuda_runtime.h>
#include <math.h>

// Problem constants (fixed shapes)
constexpr int NN = 100000;   // nodes
constexpr int EE = 1000000;  // edges
constexpr int DD = 80;       // hidden dim
constexpr int HH = 8;        // heads
constexpr int DK = 10;       // per-head dim
constexpr int LL = 10;       // layers

// ---------------- device scratch (no allocations allowed) ----------------
__device__ float g_h[NN * DD];
__device__ float g_q[NN * DD];
__device__ float g_k[NN * DD];
__device__ float g_v[NN * DD];
__device__ float g_attn[NN * DD];
__device__ float g_ffn[NN * 2 * DD];
__device__ float g_score[EE * HH];
__device__ float g_r0[NN * 40];
__device__ float g_r1[NN * 20];
__device__ int g_cnt[NN];
__device__ int g_off[NN + 1];
__device__ int g_cur[NN];
__device__ int g_ssrc[EE];
__device__ int g_sdst[EE];

// ---------------- CSR build ----------------
__global__ void zero_cnt_kernel() {
    int t = blockIdx.x * blockDim.x + threadIdx.x;
    if (t < NN) g_cnt[t] = 0;
}

__global__ void hist_kernel(const int* __restrict__ dst) {
    int e = blockIdx.x * blockDim.x + threadIdx.x;
    if (e < EE) atomicAdd(&g_cnt[dst[e]], 1);
}

// single-block scan: 1024 threads, each owns a contiguous chunk
__global__ void scan_kernel() {
    __shared__ int sums[1024];
    const int t = threadIdx.x;
    const int CH = (NN + 1023) / 1024;  // 98
    int b = t * CH;
    int e2 = b + CH; if (e2 > NN) e2 = NN;
    int s = 0;
    for (int i = b; i < e2; i++) s += g_cnt[i];
    sums[t] = s;
    __syncthreads();
    for (int ofs = 1; ofs < 1024; ofs <<= 1) {
        int v = (t >= ofs) ? sums[t - ofs] : 0;
        __syncthreads();
        sums[t] += v;
        __syncthreads();
    }
    int run = (t > 0) ? sums[t - 1] : 0;
    for (int i = b; i < e2; i++) {
        g_off[i] = run;
        g_cur[i] = run;
        run += g_cnt[i];
    }
    if (t == 1023) g_off[NN] = run;
}

__global__ void scatter_kernel(const int* __restrict__ src, const int* __restrict__ dst) {
    int e = blockIdx.x * blockDim.x + threadIdx.x;
    if (e >= EE) return;
    int d = dst[e];
    int p = atomicAdd(&g_cur[d], 1);
    g_ssrc[p] = src[e];
    g_sdst[p] = d;
}

// ---------------- tiled GEMM: C[M,NC] = act(A[M,KTOT] @ W + bias (+res)) ----------------
// Block: 256 threads (16x16), 64 rows x NC cols per block. K chunked at 80 so
// static smem stays under 48KB. Register blocking 4 rows x (NC/16) cols.
template <int KTOT, int NC, bool BIAS, bool RELU, int NRES>
__global__ void __launch_bounds__(256)
gemm_tiled(const float* __restrict__ A, int lda,
           const float* __restrict__ W, int ldw,
           const float* __restrict__ bias,
           const float* __restrict__ res,
           float* __restrict__ C, int ldc, int M) {
    constexpr int KT = (KTOT > 80) ? 80 : KTOT;
    static_assert(KTOT <= 80 || (KTOT % 80) == 0, "K chunking");
    constexpr int TN = NC / 16;
    __shared__ __align__(16) float Ws[KT * NC];
    __shared__ __align__(16) float As[KT * 64];

    const int tid = threadIdx.x;
    const int tx = tid & 15;
    const int ty = tid >> 4;
    const int row0 = blockIdx.x * 64;

    float acc[4][TN];
#pragma unroll
    for (int i = 0; i < 4; i++)
#pragma unroll
        for (int j = 0; j < TN; j++) acc[i][j] = 0.f;

    for (int k0 = 0; k0 < KTOT; k0 += KT) {
        // load weight chunk [KT x NC]
        for (int idx = tid; idx < KT * NC; idx += 256) {
            int kk = idx / NC, c = idx - kk * NC;
            Ws[idx] = W[(k0 + kk) * ldw + c];
        }
        // load A tile, transposed to [KT][64]
        for (int idx = tid; idx < 64 * KT; idx += 256) {
            int r = idx / KT, kk = idx - r * KT;
            int gr = row0 + r;
            As[kk * 64 + r] = (gr < M) ? A[gr * lda + k0 + kk] : 0.f;
        }
        __syncthreads();
#pragma unroll 4
        for (int k = 0; k < KT; ++k) {
            float4 av = *reinterpret_cast<const float4*>(&As[k * 64 + ty * 4]);
#pragma unroll
            for (int j = 0; j < TN; ++j) {
                float w = Ws[k * NC + tx + j * 16];
                acc[0][j] = fmaf(av.x, w, acc[0][j]);
                acc[1][j] = fmaf(av.y, w, acc[1][j]);
                acc[2][j] = fmaf(av.z, w, acc[2][j]);
                acc[3][j] = fmaf(av.w, w, acc[3][j]);
            }
        }
        __syncthreads();
    }

#pragma unroll
    for (int i = 0; i < 4; i++) {
        int gr = row0 + ty * 4 + i;
        if (gr >= M) break;
#pragma unroll
        for (int j = 0; j < TN; j++) {
            int c = tx + j * 16;
            float v = acc[i][j];
            if (BIAS) v += bias[c];
            if (NRES >= 1) v += res[gr * ldc + c];
            if (RELU) v = fmaxf(v, 0.f);
            C[gr * ldc + c] = v;
        }
    }
}

// ---------------- attention: scores over sorted edges ----------------
__global__ void score_kernel() {
    int t = blockIdx.x * blockDim.x + threadIdx.x;
    if (t >= EE * HH) return;
    int j = t >> 3;
    int hd = t & 7;
    int s = g_ssrc[j];
    int d = g_sdst[j];
    const float* kp = g_k + s * DD + hd * DK;
    const float* qp = g_q + d * DD + hd * DK;
    float acc = 0.f;
#pragma unroll
    for (int k = 0; k < DK; k++) acc = fmaf(kp[k], qp[k], acc);
    acc *= 0.31622776601683794f;  // 1/sqrt(10)
    acc = fminf(fmaxf(acc, -5.f), 5.f);
    g_score[t] = expf(acc);
}

// aggregation: thread per (node, dim); segment scan over CSR, fused z-normalize
__global__ void agg_kernel() {
    int lt = threadIdx.x;  // blockDim = 160: two nodes per block
    int half = (lt >= 80) ? 1 : 0;
    int node = blockIdx.x * 2 + half;
    int d = lt - half * 80;
    int h = d / DK;
    int beg = g_off[node];
    int end = g_off[node + 1];
    float wv = 0.f, z = 0.f;
    for (int j = beg; j < end; j++) {
        float s = g_score[j * HH + h];
        wv = fmaf(s, g_v[g_ssrc[j] * DD + d], wv);
        z += s;
    }
    g_attn[node * DD + d] = wv / (z + 1e-6f);
}

// ---------------- small FC (readout stages) ----------------
template <int K, int NC, bool RELU>
__global__ void simple_fc(const float* __restrict__ A, const float* __restrict__ W,
                          const float* __restrict__ b, float* __restrict__ C, int M) {
    int t = blockIdx.x * blockDim.x + threadIdx.x;
    if (t >= M * NC) return;
    int row = t / NC;
    int col = t - row * NC;
    float acc = b[col];
    const float* ap = A + row * K;
#pragma unroll 4
    for (int k = 0; k < K; k++) acc = fmaf(ap[k], W[k * NC + col], acc);
    if (RELU) acc = fmaxf(acc, 0.f);
    C[t] = acc;
}

// ---------------- launcher ----------------
extern "C" void kernel_launch(void* const* d_in, const int* in_sizes, int n_in,
                              void* d_out, int out_size) {
    const float* x   = (const float*)d_in[0];
    const int*   ei  = (const int*)d_in[1];
    const float* We  = (const float*)d_in[2];
    const float* be  = (const float*)d_in[3];
    const float* Wq  = (const float*)d_in[4];
    const float* Wk  = (const float*)d_in[5];
    const float* Wv  = (const float*)d_in[6];
    const float* Wo  = (const float*)d_in[7];
    const float* bo  = (const float*)d_in[8];
    const float* W1  = (const float*)d_in[9];
    const float* b1  = (const float*)d_in[10];
    const float* W2  = (const float*)d_in[11];
    const float* b2  = (const float*)d_in[12];
    const float* Wr0 = (const float*)d_in[13];
    const float* br0 = (const float*)d_in[14];
    const float* Wr1 = (const float*)d_in[15];
    const float* br1 = (const float*)d_in[16];
    const float* Wr2 = (const float*)d_in[17];
    const float* br2 = (const float*)d_in[18];
    float* out = (float*)d_out;

    const int* src = ei;        // edge_index[0]
    const int* dst = ei + EE;   // edge_index[1]

    // resolve device-global scratch addresses
    float *p_h, *p_q, *p_k, *p_v, *p_attn, *p_ffn, *p_r0, *p_r1;
    cudaGetSymbolAddress((void**)&p_h, g_h);
    cudaGetSymbolAddress((void**)&p_q, g_q);
    cudaGetSymbolAddress((void**)&p_k, g_k);
    cudaGetSymbolAddress((void**)&p_v, g_v);
    cudaGetSymbolAddress((void**)&p_attn, g_attn);
    cudaGetSymbolAddress((void**)&p_ffn, g_ffn);
    cudaGetSymbolAddress((void**)&p_r0, g_r0);
    cudaGetSymbolAddress((void**)&p_r1, g_r1);

    const int GB = (NN + 63) / 64;  // 1563 gemm blocks

    // --- CSR build (once per launch) ---
    zero_cnt_kernel<<<(NN + 255) / 256, 256>>>();
    hist_kernel<<<(EE + 255) / 256, 256>>>(dst);
    scan_kernel<<<1, 1024>>>();
    scatter_kernel<<<(EE + 255) / 256, 256>>>(src, dst);

    // --- embedding: h = x @ We + be ---
    gemm_tiled<9, 80, true, false, 0><<<GB, 256>>>(x, 9, We, 80, be, nullptr, p_h, 80, NN);

    // --- layers ---
    for (int l = 0; l < LL; l++) {
        const float* wq = Wq + (size_t)l * DD * DD;
        const float* wk = Wk + (size_t)l * DD * DD;
        const float* wv = Wv + (size_t)l * DD * DD;
        const float* wo = Wo + (size_t)l * DD * DD;
        const float* bol = bo + (size_t)l * DD;
        const float* w1 = W1 + (size_t)l * DD * 2 * DD;
        const float* b1l = b1 + (size_t)l * 2 * DD;
        const float* w2 = W2 + (size_t)l * 2 * DD * DD;
        const float* b2l = b2 + (size_t)l * DD;

        // Q/K/V projections (no bias)
        gemm_tiled<80, 80, false, false, 0><<<GB, 256>>>(p_h, 80, wq, 80, nullptr, nullptr, p_q, 80, NN);
        gemm_tiled<80, 80, false, false, 0><<<GB, 256>>>(p_h, 80, wk, 80, nullptr, nullptr, p_k, 80, NN);
        gemm_tiled<80, 80, false, false, 0><<<GB, 256>>>(p_h, 80, wv, 80, nullptr, nullptr, p_v, 80, NN);

        // edge scores + segment-softmax aggregation
        score_kernel<<<(EE * HH) / 256, 256>>>();
        agg_kernel<<<NN / 2, 160>>>();

        // O-proj + residual (in-place on h)
        gemm_tiled<80, 80, true, false, 1><<<GB, 256>>>(p_attn, 80, wo, 80, bol, p_h, p_h, 80, NN);

        // FFN1: relu(h @ W1 + b1), 160 cols split into two 80-col launches
        gemm_tiled<80, 80, true, true, 0><<<GB, 256>>>(p_h, 80, w1, 160, b1l, nullptr, p_ffn, 160, NN);
        gemm_tiled<80, 80, true, true, 0><<<GB, 256>>>(p_h, 80, w1 + 80, 160, b1l + 80, nullptr, p_ffn + 80, 160, NN);

        // FFN2: h = h + t @ W2 + b2 (K=160 chunked internally)
        gemm_tiled<160, 80, true, false, 1><<<GB, 256>>>(p_ffn, 160, w2, 80, b2l, p_h, p_h, 80, NN);
    }

    // --- readout: 80 -> 40 -> 20 -> 4 ---
    simple_fc<80, 40, true><<<(NN * 40 + 255) / 256, 256>>>(p_h, Wr0, br0, p_r0, NN);
    simple_fc<40, 20, true><<<(NN * 20 + 255) / 256, 256>>>(p_r0, Wr1, br1, p_r1, NN);
    simple_fc<20, 4, false><<<(NN * 4 + 255) / 256, 256>>>(p_r1, Wr2, br2, out, NN);
}